// round 1
// baseline (speedup 1.0000x reference)
#include <cuda_runtime.h>
#include <math.h>

// Problem constants
#define BB 8
#define NN 4096
#define CC 768
#define HH 8
#define DD 96
#define C3 2304
#define BH (BB*HH)
#define SPLITS 8

// Scratch (device globals — allocation-free kernel_launch)
__device__ float g_q[BB*HH*DD*NN];     // [b][h][d][n]
__device__ float g_k[BB*HH*DD*NN];
__device__ float g_v[BB*HH*DD*NN];
__device__ float g_rq[BB*HH*DD];       // 1/||q_row||
__device__ float g_rk[BB*HH*DD];
__device__ float g_part[SPLITS*BH*DD*DD];
__device__ float g_attn[BH*DD*DD];
__device__ float g_yt[BB*HH*DD*NN];    // y transposed: [b][h][d][n]

// ---------------------------------------------------------------------------
// Kernel 1: qkv = x @ W_qkv, scatter-write into q/k/v [B,H,D,N]
// Tile: BM=128, BN=64, BK=16, 256 threads, 8x4 per thread.
// ---------------------------------------------------------------------------
__global__ __launch_bounds__(256) void gemm_qkv_kernel(
    const float* __restrict__ x, const float* __restrict__ w)
{
    __shared__ float As[16][132];   // [kk][m], padded stride vs bank conflicts
    __shared__ float Bs[16][64];    // [kk][nn]
    const int tid = threadIdx.x;
    const int rowBase = blockIdx.y * 128;
    const int colBase = blockIdx.x * 64;
    const int tx = tid & 15;
    const int ty = tid >> 4;

    float acc[8][4];
#pragma unroll
    for (int i = 0; i < 8; i++)
#pragma unroll
        for (int j = 0; j < 4; j++) acc[i][j] = 0.f;

    for (int k0 = 0; k0 < CC; k0 += 16) {
#pragma unroll
        for (int p = 0; p < 8; p++) {
            int idx = p * 256 + tid;
            int kk = idx & 15, m = idx >> 4;
            As[kk][m] = x[(rowBase + m) * CC + k0 + kk];
        }
#pragma unroll
        for (int p = 0; p < 4; p++) {
            int idx = p * 256 + tid;
            int nn2 = idx & 63, kk = idx >> 6;
            Bs[kk][nn2] = w[(k0 + kk) * C3 + colBase + nn2];
        }
        __syncthreads();
#pragma unroll
        for (int kk = 0; kk < 16; kk++) {
            float4 a0 = *(const float4*)&As[kk][ty * 8];
            float4 a1 = *(const float4*)&As[kk][ty * 8 + 4];
            float4 b0 = *(const float4*)&Bs[kk][tx * 4];
            float af[8] = {a0.x, a0.y, a0.z, a0.w, a1.x, a1.y, a1.z, a1.w};
            float bf[4] = {b0.x, b0.y, b0.z, b0.w};
#pragma unroll
            for (int i = 0; i < 8; i++)
#pragma unroll
                for (int j = 0; j < 4; j++)
                    acc[i][j] = fmaf(af[i], bf[j], acc[i][j]);
        }
        __syncthreads();
    }

    // Scatter: col j -> (h = j/288, d = (j%288)/3, s = j%3)
#pragma unroll
    for (int i = 0; i < 8; i++) {
        int r = rowBase + ty * 8 + i;
        int b = r >> 12;          // / 4096
        int n = r & 4095;
#pragma unroll
        for (int j = 0; j < 4; j++) {
            int col = colBase + tx * 4 + j;
            int h   = col / 288;
            int rem = col - h * 288;
            int d   = rem / 3;
            int s   = rem - d * 3;
            float* dst = (s == 0) ? g_q : (s == 1) ? g_k : g_v;
            dst[((b * HH + h) * DD + d) * NN + n] = acc[i][j];
        }
    }
}

// ---------------------------------------------------------------------------
// Kernel 2: per-(b,h,d) inverse L2 norm over N for q (y=0) and k (y=1)
// ---------------------------------------------------------------------------
__global__ __launch_bounds__(256) void norm_kernel()
{
    const int row = blockIdx.x;
    const float* src = (blockIdx.y == 0) ? g_q : g_k;
    float*       dst = (blockIdx.y == 0) ? g_rq : g_rk;
    const float* p = src + (size_t)row * NN;
    float s = 0.f;
    for (int i = threadIdx.x; i < NN; i += 256) {
        float v = p[i];
        s = fmaf(v, v, s);
    }
#pragma unroll
    for (int off = 16; off; off >>= 1) s += __shfl_down_sync(0xffffffffu, s, off);
    __shared__ float ws[8];
    if ((threadIdx.x & 31) == 0) ws[threadIdx.x >> 5] = s;
    __syncthreads();
    if (threadIdx.x < 8) {
        float t = ws[threadIdx.x];
#pragma unroll
        for (int off = 4; off; off >>= 1) t += __shfl_down_sync(0xffu, t, off);
        if (threadIdx.x == 0) dst[row] = rsqrtf(t);
    }
}

// ---------------------------------------------------------------------------
// Kernel 3: raw cross-covariance partials: part[sp][bh][d][e] = sum_n q[d,n]k[e,n]
// over n-chunk of 512. Block: 96x96 out, 256 threads, 6x6 per thread, BK=32.
// ---------------------------------------------------------------------------
__global__ __launch_bounds__(256) void attn_part_kernel()
{
    __shared__ float Qs[32][97];   // [n'][d], stride 97 = conflict-free
    __shared__ float Ks[32][97];
    const int tid = threadIdx.x;
    const int bh = blockIdx.x;
    const int n0 = blockIdx.y * (NN / SPLITS);
    const float* qp = g_q + (size_t)bh * DD * NN;
    const float* kp = g_k + (size_t)bh * DD * NN;
    const int tx = tid & 15;
    const int ty = tid >> 4;

    float acc[6][6];
#pragma unroll
    for (int i = 0; i < 6; i++)
#pragma unroll
        for (int j = 0; j < 6; j++) acc[i][j] = 0.f;

    for (int nc = 0; nc < NN / SPLITS; nc += 32) {
#pragma unroll
        for (int p = 0; p < 12; p++) {
            int idx = p * 256 + tid;
            int nn2 = idx & 31, d = idx >> 5;
            Qs[nn2][d] = qp[d * NN + n0 + nc + nn2];
            Ks[nn2][d] = kp[d * NN + n0 + nc + nn2];
        }
        __syncthreads();
#pragma unroll
        for (int kk = 0; kk < 32; kk++) {
            float fq[6], fk[6];
#pragma unroll
            for (int i = 0; i < 6; i++) fq[i] = Qs[kk][ty * 6 + i];
#pragma unroll
            for (int j = 0; j < 6; j++) fk[j] = Ks[kk][tx * 6 + j];
#pragma unroll
            for (int i = 0; i < 6; i++)
#pragma unroll
                for (int j = 0; j < 6; j++)
                    acc[i][j] = fmaf(fq[i], fk[j], acc[i][j]);
        }
        __syncthreads();
    }

    float* dst = g_part + ((size_t)blockIdx.y * BH + bh) * DD * DD;
#pragma unroll
    for (int i = 0; i < 6; i++)
#pragma unroll
        for (int j = 0; j < 6; j++)
            dst[(ty * 6 + i) * DD + tx * 6 + j] = acc[i][j];
}

// ---------------------------------------------------------------------------
// Kernel 4: reduce split-K partials, apply norms * temp, softmax over e.
// One block (128 threads, 96 active) per (bh, d) row.
// ---------------------------------------------------------------------------
__global__ __launch_bounds__(128) void softmax_kernel(const float* __restrict__ temp)
{
    const int bhd = blockIdx.x;
    const int bh = bhd / DD;
    const int d  = bhd - bh * DD;
    const int h  = bh & (HH - 1);
    const int e  = threadIdx.x;

    float raw = 0.f;
    float val = -1e30f;
    if (e < DD) {
        float s = 0.f;
#pragma unroll
        for (int sp = 0; sp < SPLITS; sp++)
            s += g_part[(((size_t)sp * BH + bh) * DD + d) * DD + e];
        raw = s * g_rq[bh * DD + d] * g_rk[bh * DD + e] * temp[h];
        val = raw;
    }

    __shared__ float red[128];
    red[e] = val;
    __syncthreads();
#pragma unroll
    for (int off = 64; off >= 1; off >>= 1) {
        if (e < off) red[e] = fmaxf(red[e], red[e + off]);
        __syncthreads();
    }
    float m = red[0];
    __syncthreads();

    float ex = (e < DD) ? expf(raw - m) : 0.f;
    red[e] = ex;
    __syncthreads();
#pragma unroll
    for (int off = 64; off >= 1; off >>= 1) {
        if (e < off) red[e] += red[e + off];
        __syncthreads();
    }
    float sum = red[0];

    if (e < DD)
        g_attn[((size_t)bh * DD + d) * DD + e] = ex / sum;
}

// ---------------------------------------------------------------------------
// Kernel 5: y_t[d][n] = sum_e attn[d][e] * v[e][n], per (bh, n-tile of 128)
// BM=96(d), BN=128(n), K=96 in chunks of 32, 256 threads, 6x8 per thread.
// ---------------------------------------------------------------------------
__global__ __launch_bounds__(256) void av_kernel()
{
    __shared__ float As_[96][33];   // [d][e'], pad stride 33
    __shared__ float Vs[32][128];   // [e'][n']
    const int tid = threadIdx.x;
    const int bh = blockIdx.x;
    const int n0 = blockIdx.y * 128;
    const float* ap = g_attn + (size_t)bh * DD * DD;
    const float* vp = g_v + (size_t)bh * DD * NN;
    const int tx = tid & 15;
    const int ty = tid >> 4;

    float acc[6][8];
#pragma unroll
    for (int i = 0; i < 6; i++)
#pragma unroll
        for (int j = 0; j < 8; j++) acc[i][j] = 0.f;

    for (int ec = 0; ec < DD; ec += 32) {
#pragma unroll
        for (int p = 0; p < 12; p++) {
            int idx = p * 256 + tid;
            int ee = idx & 31, d = idx >> 5;
            As_[d][ee] = ap[d * DD + ec + ee];
        }
#pragma unroll
        for (int p = 0; p < 16; p++) {
            int idx = p * 256 + tid;
            int nn2 = idx & 127, ee = idx >> 7;
            Vs[ee][nn2] = vp[(ec + ee) * NN + n0 + nn2];
        }
        __syncthreads();
#pragma unroll
        for (int kk = 0; kk < 32; kk++) {
            float fa[6];
#pragma unroll
            for (int i = 0; i < 6; i++) fa[i] = As_[ty * 6 + i][kk];
            float4 v0 = *(const float4*)&Vs[kk][tx * 8];
            float4 v1 = *(const float4*)&Vs[kk][tx * 8 + 4];
            float fv[8] = {v0.x, v0.y, v0.z, v0.w, v1.x, v1.y, v1.z, v1.w};
#pragma unroll
            for (int i = 0; i < 6; i++)
#pragma unroll
                for (int j = 0; j < 8; j++)
                    acc[i][j] = fmaf(fa[i], fv[j], acc[i][j]);
        }
        __syncthreads();
    }

    float* yp = g_yt + (size_t)bh * DD * NN;
#pragma unroll
    for (int i = 0; i < 6; i++) {
        int d = ty * 6 + i;
        float4 o0 = {acc[i][0], acc[i][1], acc[i][2], acc[i][3]};
        float4 o1 = {acc[i][4], acc[i][5], acc[i][6], acc[i][7]};
        *(float4*)&yp[d * NN + n0 + tx * 8]     = o0;
        *(float4*)&yp[d * NN + n0 + tx * 8 + 4] = o1;
    }
}

// ---------------------------------------------------------------------------
// Kernel 6: out = y @ W_proj + b_proj, gathering A from g_yt [b][c'][n].
// Tile: BM=128, BN=64, BK=16, 256 threads, 8x4 per thread.
// ---------------------------------------------------------------------------
__global__ __launch_bounds__(256) void gemm_proj_kernel(
    const float* __restrict__ w, const float* __restrict__ bias,
    float* __restrict__ out)
{
    __shared__ float As[16][132];
    __shared__ float Bs[16][64];
    const int tid = threadIdx.x;
    const int rowBase = blockIdx.y * 128;
    const int colBase = blockIdx.x * 64;
    const int b     = rowBase >> 12;     // rows never straddle a batch (128 | 4096)
    const int nBase = rowBase & 4095;
    const int tx = tid & 15;
    const int ty = tid >> 4;

    float acc[8][4];
#pragma unroll
    for (int i = 0; i < 8; i++)
#pragma unroll
        for (int j = 0; j < 4; j++) acc[i][j] = 0.f;

    for (int k0 = 0; k0 < CC; k0 += 16) {
        // A tile gathered from y_t: element (m, kk) = g_yt[(b*CC + k0+kk)*NN + nBase+m]
#pragma unroll
        for (int p = 0; p < 8; p++) {
            int idx = p * 256 + tid;
            int m = idx & 127, kk = idx >> 7;
            As[kk][m] = g_yt[((size_t)b * CC + k0 + kk) * NN + nBase + m];
        }
#pragma unroll
        for (int p = 0; p < 4; p++) {
            int idx = p * 256 + tid;
            int nn2 = idx & 63, kk = idx >> 6;
            Bs[kk][nn2] = w[(k0 + kk) * CC + colBase + nn2];
        }
        __syncthreads();
#pragma unroll
        for (int kk = 0; kk < 16; kk++) {
            float4 a0 = *(const float4*)&As[kk][ty * 8];
            float4 a1 = *(const float4*)&As[kk][ty * 8 + 4];
            float4 b0 = *(const float4*)&Bs[kk][tx * 4];
            float af[8] = {a0.x, a0.y, a0.z, a0.w, a1.x, a1.y, a1.z, a1.w};
            float bf[4] = {b0.x, b0.y, b0.z, b0.w};
#pragma unroll
            for (int i = 0; i < 8; i++)
#pragma unroll
                for (int j = 0; j < 4; j++)
                    acc[i][j] = fmaf(af[i], bf[j], acc[i][j]);
        }
        __syncthreads();
    }

#pragma unroll
    for (int i = 0; i < 8; i++) {
        int r = rowBase + ty * 8 + i;
#pragma unroll
        for (int j = 0; j < 4; j++) {
            int col = colBase + tx * 4 + j;
            out[(size_t)r * CC + col] = acc[i][j] + bias[col];
        }
    }
}

// ---------------------------------------------------------------------------
extern "C" void kernel_launch(void* const* d_in, const int* in_sizes, int n_in,
                              void* d_out, int out_size)
{
    const float* x      = (const float*)d_in[0];
    const float* w_qkv  = (const float*)d_in[1];
    const float* w_proj = (const float*)d_in[2];
    const float* b_proj = (const float*)d_in[3];
    const float* temp   = (const float*)d_in[4];
    float* out = (float*)d_out;

    gemm_qkv_kernel<<<dim3(C3 / 64, (BB * NN) / 128), 256>>>(x, w_qkv);
    norm_kernel<<<dim3(BH * DD, 2), 256>>>();
    attn_part_kernel<<<dim3(BH, SPLITS), 256>>>();
    softmax_kernel<<<BH * DD, 128>>>(temp);
    av_kernel<<<dim3(BH, NN / 128), 256>>>();
    gemm_proj_kernel<<<dim3(CC / 64, (BB * NN) / 128), 256>>>(w_proj, b_proj, out);
}